// round 15
// baseline (speedup 1.0000x reference)
#include <cuda_runtime.h>
#include <cuda_fp16.h>
#include <math.h>
#include <stdint.h>

#define B_  4
#define S_  2048
#define D_  1024
#define M_  512
#define H_  8
#define R_  (B_*S_)   // 8192 token rows

// ---------------- scratch (device globals: no allocation) ----------------
__device__ __half g_x  [R_*D_];
__device__ __half g_mem[R_*M_];
__device__ __half g_qkv[3*R_*M_];      // [3][B][H][S][64]
__device__ __half g_ctx[R_*M_];
__device__ __half g_h1 [R_*D_];
__device__ float  g_h2 [R_*D_];        // fp32 staging (w1 x-part, then w2 out)
__device__ float  g_bqkv[3*M_];
__device__ float  g_b1p [D_];          // b1 + bo @ W1b
__device__ int    g_rowcnt[64];        // w2 row-block completion counters
// weights transposed [N][K], fp16
__device__ __half g_wenc[M_*D_];
__device__ __half g_wqkv[3*M_*M_];
__device__ __half g_wo_nt[M_*M_];      // Wo NON-transposed fp16 [k][j]
__device__ __half g_w1  [D_*(D_+M_)];
__device__ __half g_w2  [D_*D_];
__device__ __half g_wfused[D_*M_];     // (Wo@W1b)^T  [1024][512]

// ---------------- helpers ----------------
__device__ __forceinline__ uint32_t smem_u32(const void* p) {
    uint32_t a;
    asm("{ .reg .u64 t; cvta.to.shared.u64 t, %1; cvt.u32.u64 %0, t; }" : "=r"(a) : "l"(p));
    return a;
}
__device__ __forceinline__ uint32_t pack_h2(float a, float b) {
    __half2 h = __floats2half2_rn(a, b);
    return *reinterpret_cast<uint32_t*>(&h);
}
__device__ __forceinline__ float gelu_exact(float v) {
    return 0.5f * v * (1.0f + erff(v * 0.70710678118654752440f));
}
__device__ __forceinline__ void cp16(uint32_t s, const void* g) {
    asm volatile("cp.async.cg.shared.global [%0], [%1], 16;" :: "r"(s), "l"(g) : "memory");
}
#define CP_COMMIT() asm volatile("cp.async.commit_group;" ::: "memory")
#define CP_WAIT0()  asm volatile("cp.async.wait_group 0;" ::: "memory")
#define CP_WAIT2()  asm volatile("cp.async.wait_group 2;" ::: "memory")

#define LDSM4(r, addr) \
    asm volatile("ldmatrix.sync.aligned.m8n8.x4.shared.b16 {%0,%1,%2,%3}, [%4];" \
        : "=r"((r)[0]), "=r"((r)[1]), "=r"((r)[2]), "=r"((r)[3]) : "r"(addr))
#define LDSM4T(r, addr) \
    asm volatile("ldmatrix.sync.aligned.m8n8.x4.trans.shared.b16 {%0,%1,%2,%3}, [%4];" \
        : "=r"((r)[0]), "=r"((r)[1]), "=r"((r)[2]), "=r"((r)[3]) : "r"(addr))

__device__ __forceinline__ void mma_f16(float* c, const uint32_t* a, uint32_t b0, uint32_t b1) {
    asm volatile("mma.sync.aligned.m16n8k16.row.col.f32.f16.f16.f32 "
        "{%0,%1,%2,%3}, {%4,%5,%6,%7}, {%8,%9}, {%0,%1,%2,%3};"
        : "+f"(c[0]), "+f"(c[1]), "+f"(c[2]), "+f"(c[3])
        : "r"(a[0]), "r"(a[1]), "r"(a[2]), "r"(a[3]), "r"(b0), "r"(b1));
}

// ---------------- single merged prep kernel --------------------------------
__global__ __launch_bounds__(256)
void prep_all(const float* __restrict__ x,
              const float* __restrict__ wenc, const float* __restrict__ wq,
              const float* __restrict__ wk,   const float* __restrict__ wv,
              const float* __restrict__ wo,   const float* __restrict__ w1,
              const float* __restrict__ w2,
              const float* __restrict__ bq, const float* __restrict__ bk,
              const float* __restrict__ bv, const float* __restrict__ bo,
              const float* __restrict__ b1)
{
    const int blk = blockIdx.x, tid = threadIdx.x;
    if (blk < 3840) {
        __shared__ float t[32][33];
        int tw = blk;
        const float* src; __half* dh; int K, N;
        if      (tw < 512)  {             src = wenc; dh = g_wenc; K = 1024; N = 512; }
        else if (tw < 768)  { tw -= 512;  src = wq; dh = g_wqkv;              K = 512; N = 512; }
        else if (tw < 1024) { tw -= 768;  src = wk; dh = g_wqkv + 512*512;    K = 512; N = 512; }
        else if (tw < 1280) { tw -= 1024; src = wv; dh = g_wqkv + 2*512*512;  K = 512; N = 512; }
        else if (tw < 2816) { tw -= 1280; src = w1; dh = g_w1; K = 1536; N = 1024; }
        else                { tw -= 2816; src = w2; dh = g_w2; K = 1024; N = 1024; }

        const int tilesx = N / 32;
        const int kb = (tw / tilesx) * 32, nb = (tw % tilesx) * 32;
        const int xx = tid & 31, yy = tid >> 5;  // 32 x 8
#pragma unroll
        for (int j = 0; j < 32; j += 8)
            t[yy + j][xx] = src[(size_t)(kb + yy + j) * N + nb + xx];
        __syncthreads();
#pragma unroll
        for (int j = 0; j < 32; j += 8)
            dh[(size_t)(nb + yy + j) * K + kb + xx] = __float2half_rn(t[xx][yy + j]);
        if (blk == 0) {
            for (int i = tid; i < 1536; i += 256)
                g_bqkv[i] = (i < 512) ? bq[i] : (i < 1024) ? bk[i - 512] : bv[i - 1024];
        }
        if (blk == 1 && tid < 64) g_rowcnt[tid] = 0;
    } else if (blk < 12032) {
        const size_t i = ((size_t)(blk - 3840) * 256 + tid) * 4;
        float4 v = *reinterpret_cast<const float4*>(x + i);
        *reinterpret_cast<uint2*>(g_x + i) = make_uint2(pack_h2(v.x, v.y), pack_h2(v.z, v.w));
    } else if (blk < 12288) {
        const size_t i = ((size_t)(blk - 12032) * 256 + tid) * 4;
        float4 v = *reinterpret_cast<const float4*>(wo + i);
        *reinterpret_cast<uint2*>(g_wo_nt + i) = make_uint2(pack_h2(v.x, v.y), pack_h2(v.z, v.w));
    } else {
        __shared__ float red[8][33];
        const int nloc = tid & 31, ksl = tid >> 5;
        const int n = (blk - 12288) * 32 + nloc;
        float s = 0.f;
        const int j0 = ksl * 64;
        for (int j = j0; j < j0 + 64; j++)
            s += bo[j] * w1[(size_t)(1024 + j) * 1024 + n];
        red[ksl][nloc] = s;
        __syncthreads();
        if (ksl == 0) {
            float t2 = b1[n];
#pragma unroll
            for (int q = 0; q < 8; q++) t2 += red[q][nloc];
            g_b1p[n] = t2;
        }
    }
}

// ================== epilogue helper ========================================
template<int EPI>
__device__ __forceinline__ void epi_store(
    float* accp, int r0, int col,
    const float* __restrict__ bias,
    void* __restrict__ o1, const float* __restrict__ i2, int ldc)
{
    const int r1 = r0 + 8;
    float b0v = 0.f, b1v = 0.f;
    if (EPI != 4 && bias) { b0v = bias[col]; b1v = bias[col + 1]; }
    float v00 = accp[0] + b0v, v01 = accp[1] + b1v;
    float v10 = accp[2] + b0v, v11 = accp[3] + b1v;
    if (EPI == 3) {
        float* C = (float*)o1;
        *reinterpret_cast<float2*>(C + (size_t)r0 * ldc + col) = make_float2(v00, v01);
        *reinterpret_cast<float2*>(C + (size_t)r1 * ldc + col) = make_float2(v10, v11);
    } else if (EPI == 4) {
        float2 p0 = *reinterpret_cast<const float2*>(i2 + (size_t)r0 * ldc + col);
        float2 p1 = *reinterpret_cast<const float2*>(i2 + (size_t)r1 * ldc + col);
        v00 = gelu_exact(p0.x + v00); v01 = gelu_exact(p0.y + v01);
        v10 = gelu_exact(p1.x + v10); v11 = gelu_exact(p1.y + v11);
        __half* Ch = (__half*)o1;
        *reinterpret_cast<uint32_t*>(Ch + (size_t)r0 * ldc + col) = pack_h2(v00, v01);
        *reinterpret_cast<uint32_t*>(Ch + (size_t)r1 * ldc + col) = pack_h2(v10, v11);
    } else {
        __half* Ch = (__half*)o1;
        if (EPI == 1) {
            const int tns = col >> 9, rem = col & 511;
            const int hh = rem >> 6, dd = rem & 63;
            size_t oa = ((((size_t)(tns*4 + (r0 >> 11)) * 8 + hh) * 2048 + (r0 & 2047)) * 64 + dd);
            size_t ob = ((((size_t)(tns*4 + (r1 >> 11)) * 8 + hh) * 2048 + (r1 & 2047)) * 64 + dd);
            *reinterpret_cast<uint32_t*>(Ch + oa) = pack_h2(v00, v01);
            *reinterpret_cast<uint32_t*>(Ch + ob) = pack_h2(v10, v11);
        } else {
            *reinterpret_cast<uint32_t*>(Ch + (size_t)r0 * ldc + col) = pack_h2(v00, v01);
            *reinterpret_cast<uint32_t*>(Ch + (size_t)r1 * ldc + col) = pack_h2(v10, v11);
        }
    }
}

// ---------------- fp16 GEMM body 128x128, 8 warps --------------------------
#define ABUF  8192
#define STAGE_BYTES (2*ABUF)
#define GEMM_SMEM (4*STAGE_BYTES)   // 65536

template<int EPI>
__device__ __forceinline__ void hgemm_body(
    char* sm_, int bm, int bn,
    const __half* __restrict__ A1, int lda1, int KA,
    const __half* __restrict__ A2, int lda2,
    const __half* __restrict__ Bt, int ldb,
    const float* __restrict__ bias,
    void* __restrict__ o1, const float* __restrict__ i2, int ldc, int K)
{
    const uint32_t sb = smem_u32(sm_);
    const int tid = threadIdx.x, wid = tid >> 5, lane = tid & 31;
    const int m0 = (wid & 3) * 32, n0 = (wid >> 2) * 64;

    float acc[2][8][4];
#pragma unroll
    for (int i = 0; i < 2; i++)
#pragma unroll
        for (int j = 0; j < 8; j++)
#pragma unroll
            for (int t = 0; t < 4; t++) acc[i][j][t] = 0.f;

    const int cpr = tid >> 2, cpk = tid & 3;
    const uint32_t cps0 = (uint32_t)(cpr * 64 + ((cpk ^ ((cpr >> 1) & 3)) << 4));
    const int cpr1 = cpr + 64;
    const uint32_t cps1 = (uint32_t)(cpr1 * 64 + ((cpk ^ ((cpr1 >> 1) & 3)) << 4));
    const int cpe = cpk * 8;

    auto LOADCP = [&](int c, int buf) {
        const int k0 = c * 32;
        const __half* ap; int ld, ko;
        if (k0 < KA) { ap = A1; ld = lda1; ko = k0; }
        else         { ap = A2; ld = lda2; ko = k0 - KA; }
        const uint32_t st = sb + buf * STAGE_BYTES;
        cp16(st + cps0,        ap + (size_t)(bm + cpr)  * ld + ko + cpe);
        cp16(st + cps1,        ap + (size_t)(bm + cpr1) * ld + ko + cpe);
        cp16(st + ABUF + cps0, Bt + (size_t)(bn + cpr)  * ldb + k0 + cpe);
        cp16(st + ABUF + cps1, Bt + (size_t)(bn + cpr1) * ldb + k0 + cpe);
    };

    const int i4 = lane >> 3, l7 = lane & 7;
    const int khalf = i4 >> 1;
    uint32_t aoffs[2], boffs[4];
#pragma unroll
    for (int mi = 0; mi < 2; mi++) {
        int row = m0 + mi * 16 + ((i4 & 1) << 3) + l7;
        aoffs[mi] = row * 64 + ((khalf ^ ((row >> 1) & 3)) << 4);
    }
#pragma unroll
    for (int nj = 0; nj < 4; nj++) {
        int row = n0 + nj * 16 + ((i4 & 1) << 3) + l7;
        boffs[nj] = row * 64 + ((khalf ^ ((row >> 1) & 3)) << 4);
    }

    const int NC = K >> 5;
    LOADCP(0, 0); CP_COMMIT();
    if (NC > 1) { LOADCP(1, 1); } CP_COMMIT();
    if (NC > 2) { LOADCP(2, 2); } CP_COMMIT();

    for (int c = 0; c < NC; c++) {
        CP_WAIT2();
        __syncthreads();
        const uint32_t bA = sb + (c & 3) * STAGE_BYTES;
        const uint32_t bB = bA + ABUF;

        uint32_t a0[2][4], a1[2][4];
        LDSM4(a0[0], bA + aoffs[0]);
        LDSM4(a0[1], bA + aoffs[1]);
        LDSM4(a1[0], bA + (aoffs[0] ^ 32));
        LDSM4(a1[1], bA + (aoffs[1] ^ 32));

        if (c + 3 < NC) { LOADCP(c + 3, (c + 3) & 3); }
        CP_COMMIT();

        uint32_t bfr[2][4];
        LDSM4(bfr[0], bB + boffs[0]);
#pragma unroll
        for (int t = 0; t < 8; t++) {
            const int nj = t & 3, ks = t >> 2;
            if (t < 7) {
                const int t2 = t + 1;
                LDSM4(bfr[t2 & 1], bB + (boffs[t2 & 3] ^ ((t2 >> 2) << 5)));
            }
            const uint32_t (*av)[4] = ks ? a1 : a0;
            const uint32_t* bv = bfr[t & 1];
            mma_f16(acc[0][nj*2],   av[0], bv[0], bv[2]);
            mma_f16(acc[0][nj*2+1], av[0], bv[1], bv[3]);
            mma_f16(acc[1][nj*2],   av[1], bv[0], bv[2]);
            mma_f16(acc[1][nj*2+1], av[1], bv[1], bv[3]);
        }
    }

    const int g = lane >> 2, tig = lane & 3;
#pragma unroll
    for (int mi = 0; mi < 2; mi++)
#pragma unroll
        for (int nf = 0; nf < 8; nf++)
            epi_store<EPI>(acc[mi][nf],
                           bm + m0 + mi * 16 + g,
                           bn + n0 + nf * 8 + tig * 2,
                           bias, o1, i2, ldc);
}

template<int EPI>
__global__ __launch_bounds__(256, 2)
void hgemm(const __half* __restrict__ A1, int lda1, int KA,
           const __half* __restrict__ A2, int lda2,
           const __half* __restrict__ Bt, int ldb,
           const float* __restrict__ bias,
           void* __restrict__ o1, const float* __restrict__ i2, int ldc, int K)
{
    extern __shared__ char sm_[];
    hgemm_body<EPI>(sm_, blockIdx.y * 128, blockIdx.x * 128,
                    A1, lda1, KA, A2, lda2, Bt, ldb, bias, o1, i2, ldc, K);
}

// -------- w2 GEMM with FUSED LayerNorm (last CTA per row-block) ------------
__global__ __launch_bounds__(256, 2)
void hgemm_w2_ln(const __half* __restrict__ h1, const __half* __restrict__ w2,
                 const float* __restrict__ b2, float* __restrict__ h2,
                 const float* __restrict__ ln_g, const float* __restrict__ ln_b,
                 float* __restrict__ out)
{
    extern __shared__ char sm_[];
    const int bm = blockIdx.y * 128, bn = blockIdx.x * 128;
    hgemm_body<3>(sm_, bm, bn, h1, D_, D_, h1, D_, w2, D_, b2, h2, nullptr, D_, D_);

    // completion count for this 128-row block
    __syncthreads();
    __threadfence();
    __shared__ int done;
    if (threadIdx.x == 0) done = atomicAdd(&g_rowcnt[blockIdx.y], 1);
    __syncthreads();
    if (done != 7) return;
    __threadfence();   // acquire: other CTAs' h2 stores

    // LayerNorm rows [bm, bm+128): warp per row, 16 rows per warp
    const int wid = threadIdx.x >> 5, lane = threadIdx.x & 31;
    for (int r = wid; r < 128; r += 8) {
        const float* row = h2 + (size_t)(bm + r) * 1024;
        float4 v[8];
        float s = 0.f;
#pragma unroll
        for (int i = 0; i < 8; i++) {
            v[i] = reinterpret_cast<const float4*>(row)[lane + i * 32];
            s += v[i].x + v[i].y + v[i].z + v[i].w;
        }
#pragma unroll
        for (int off = 16; off; off >>= 1) s += __shfl_xor_sync(0xffffffffu, s, off);
        const float mean = s * (1.0f / 1024.0f);
        float ss = 0.f;
#pragma unroll
        for (int i = 0; i < 8; i++) {
            v[i].x -= mean; v[i].y -= mean; v[i].z -= mean; v[i].w -= mean;
            ss += v[i].x*v[i].x + v[i].y*v[i].y + v[i].z*v[i].z + v[i].w*v[i].w;
        }
#pragma unroll
        for (int off = 16; off; off >>= 1) ss += __shfl_xor_sync(0xffffffffu, ss, off);
        const float inv = rsqrtf(ss * (1.0f / 1024.0f) + 1e-5f);
        float* orow = out + (size_t)(bm + r) * 1024;
#pragma unroll
        for (int i = 0; i < 8; i++) {
            const int c4 = (lane + i * 32) * 4;
            float4 o4;
            o4.x = v[i].x * inv * ln_g[c4    ] + ln_b[c4    ];
            o4.y = v[i].y * inv * ln_g[c4 + 1] + ln_b[c4 + 1];
            o4.z = v[i].z * inv * ln_g[c4 + 2] + ln_b[c4 + 2];
            o4.w = v[i].w * inv * ln_g[c4 + 3] + ln_b[c4 + 3];
            reinterpret_cast<float4*>(orow)[lane + i * 32] = o4;
        }
    }
}

// -------- fused: mem GEMM (256 CTAs) + wfused GEMM (32 CTAs), one wave ----
__global__ __launch_bounds__(256, 2)
void fused_mem_wf(const __half* __restrict__ xh, const __half* __restrict__ wenc,
                  const float* __restrict__ b_enc, __half* __restrict__ mem,
                  const __half* __restrict__ w1, const __half* __restrict__ wo_nt,
                  __half* __restrict__ wfused)
{
    extern __shared__ char sm_[];
    if (blockIdx.x < 256) {
        const int bn = (blockIdx.x & 3) * 128;
        const int bm = (blockIdx.x >> 2) * 128;
        hgemm_body<0>(sm_, bm, bn, xh, D_, D_, xh, D_, wenc, D_, b_enc,
                      mem, nullptr, M_, D_);
    } else {
        const int idx = blockIdx.x - 256;
        const int bn = (idx & 3) * 128;
        const int bm = (idx >> 2) * 128;
        hgemm_body<0>(sm_, bm, bn, w1 + 1024, D_ + M_, M_, w1 + 1024, D_ + M_,
                      wo_nt, M_, nullptr, wfused, nullptr, M_, M_);
    }
}

// ------- fp16 flash attention body: 128-q tile, 8 warps, fixed-shift ------
#define AT_PITCH 144
#define AT_QBUF  9216
#define AT_Q2BUF (128*AT_PITCH)
#define AT_STAGE (2*AT_QBUF)
#define LOG2E 1.44269504088896f

__device__ __forceinline__ void attn_body(
    char* sm_, int abid,
    const __half* __restrict__ qkv, const float* __restrict__ ocr,
    __half* __restrict__ ctx)
{
    const uint32_t sb = smem_u32(sm_);
    const int tid = threadIdx.x, wid = tid >> 5, lane = tid & 31;
    const int bh = abid >> 4;
    const int qt = abid & 15;
    const int b = bh >> 3, h = bh & 7;
    const int qb = qt * 128;
    const float esc2 = (ocr[h] - 8.0f) * LOG2E;

    const size_t base = (size_t)bh * S_ * 64;
    const size_t ksec = (size_t)R_ * M_;
    const size_t vsec = 2 * ksec;

#pragma unroll
    for (int i = 0; i < 4; i++) {
        int idx = tid + i * 256;
        int r = idx >> 3, cc = (idx & 7) * 16;
        cp16(sb + r * AT_PITCH + cc, (const char*)(qkv + base + (size_t)(qb + r) * 64) + cc);
    }

    auto LOADKV = [&](int c, int buf) {
        const int kb = c * 64;
        const uint32_t st = sb + AT_Q2BUF + buf * AT_STAGE;
#pragma unroll
        for (int i = 0; i < 2; i++) {
            int idx = tid + i * 256;
            int r = idx >> 3, cc = (idx & 7) * 16;
            size_t go = base + (size_t)(kb + r) * 64;
            cp16(st + r * AT_PITCH + cc,            (const char*)(qkv + ksec + go) + cc);
            cp16(st + AT_QBUF + r * AT_PITCH + cc,  (const char*)(qkv + vsec + go) + cc);
        }
    };

    LOADKV(0, 0);
    CP_COMMIT();

    const int q0 = wid * 16;
    const int i4 = lane >> 3, l7 = lane & 7;
    const int g = lane >> 2, tig = lane & 3;
    const uint32_t aoff = (uint32_t)((q0 + ((i4 & 1) << 3) + l7) * AT_PITCH + ((i4 >> 1) << 4));
    uint32_t koffs[4];
#pragma unroll
    for (int nj = 0; nj < 4; nj++)
        koffs[nj] = (uint32_t)((nj * 16 + ((i4 & 1) << 3) + l7) * AT_PITCH + ((i4 >> 1) << 4));
    const int vrow = ((lane >> 4) & 1) * 8 + (lane & 7);
    const int vcol = ((lane >> 3) & 1) * 8;
    uint32_t voffs[4];
#pragma unroll
    for (int ks = 0; ks < 4; ks++)
        voffs[ks] = (uint32_t)(AT_QBUF + (16 * ks + vrow) * AT_PITCH + vcol * 2);

    float l0r = 0.f, l1r = 0.f;
    float o[8][4];
#pragma unroll
    for (int j = 0; j < 8; j++)
#pragma unroll
        for (int t = 0; t < 4; t++) o[j][t] = 0.f;

    uint32_t qv[4][4];
    bool qloaded = false;

    for (int c = 0; c < 32; c++) {
        CP_WAIT0();
        __syncthreads();
        if (c + 1 < 32) { LOADKV(c + 1, (c + 1) & 1); CP_COMMIT(); }

        if (!qloaded) {
#pragma unroll
            for (int ks = 0; ks < 4; ks++) LDSM4(qv[ks], sb + aoff + ks * 32);
            qloaded = true;
        }

        const uint32_t st = sb + AT_Q2BUF + (c & 1) * AT_STAGE;

        float s[8][4];
#pragma unroll
        for (int j = 0; j < 8; j++)
#pragma unroll
            for (int t = 0; t < 4; t++) s[j][t] = 0.f;
#pragma unroll
        for (int ks = 0; ks < 4; ks++) {
#pragma unroll
            for (int nj = 0; nj < 4; nj++) {
                uint32_t kv[4];
                LDSM4(kv, st + koffs[nj] + ks * 32);
                mma_f16(s[nj*2],   qv[ks], kv[0], kv[2]);
                mma_f16(s[nj*2+1], qv[ks], kv[1], kv[3]);
            }
        }

#pragma unroll
        for (int j = 0; j < 8; j++) {
            s[j][0] = exp2f(fmaf(s[j][0], 0.125f * LOG2E, esc2));
            s[j][1] = exp2f(fmaf(s[j][1], 0.125f * LOG2E, esc2));
            s[j][2] = exp2f(fmaf(s[j][2], 0.125f * LOG2E, esc2));
            s[j][3] = exp2f(fmaf(s[j][3], 0.125f * LOG2E, esc2));
            l0r += s[j][0] + s[j][1];
            l1r += s[j][2] + s[j][3];
        }

#pragma unroll
        for (int ks = 0; ks < 4; ks++) {
            uint32_t pa[4];
            pa[0] = pack_h2(s[2*ks][0],   s[2*ks][1]);
            pa[1] = pack_h2(s[2*ks][2],   s[2*ks][3]);
            pa[2] = pack_h2(s[2*ks+1][0], s[2*ks+1][1]);
            pa[3] = pack_h2(s[2*ks+1][2], s[2*ks+1][3]);
#pragma unroll
            for (int d0 = 0; d0 < 4; d0++) {
                uint32_t vv[4];
                LDSM4T(vv, st + voffs[ks] + d0 * 32);
                const int dj = d0 * 2;
                mma_f16(o[dj],   pa, vv[0], vv[2]);
                mma_f16(o[dj+1], pa, vv[1], vv[3]);
            }
        }
    }

    l0r += __shfl_xor_sync(0xffffffffu, l0r, 1);
    l0r += __shfl_xor_sync(0xffffffffu, l0r, 2);
    l1r += __shfl_xor_sync(0xffffffffu, l1r, 1);
    l1r += __shfl_xor_sync(0xffffffffu, l1r, 2);

    const float rl0 = 1.0f / l0r, rl1 = 1.0f / l1r;
    const int row0 = b * S_ + qb + q0 + g;
    const int row1 = row0 + 8;
#pragma unroll
    for (int j = 0; j < 8; j++) {
        const int col = h * 64 + j * 8 + tig * 2;
        *reinterpret_cast<uint32_t*>(ctx + (size_t)row0 * M_ + col) = pack_h2(o[j][0]*rl0, o[j][1]*rl0);
        *reinterpret_cast<uint32_t*>(ctx + (size_t)row1 * M_ + col) = pack_h2(o[j][2]*rl1, o[j][3]*rl1);
    }
}

// ------ fused: attention FIRST (LPT), then x@W1-top GEMM CTAs -------------
#define GX_ATTN 512
#define GX_GEMM 512
__global__ __launch_bounds__(256, 2)
void fused_attn_w1(const __half* __restrict__ xh, const __half* __restrict__ w1,
                   const float* __restrict__ b1p, float* __restrict__ h2o,
                   const __half* __restrict__ qkv, const float* __restrict__ ocr,
                   __half* __restrict__ ctx)
{
    extern __shared__ char sm_[];
    if (blockIdx.x < GX_ATTN) {
        attn_body(sm_, blockIdx.x, qkv, ocr, ctx);
    } else {
        const int id = blockIdx.x - GX_ATTN;
        const int bm = (id & 63) * 128;
        const int bn = (id >> 6) * 128;
        hgemm_body<3>(sm_, bm, bn, xh, D_, D_, xh, D_,
                      w1, D_ + M_, b1p, h2o, nullptr, D_, D_);
    }
}

// ---------------- launch ---------------------------------------------------
extern "C" void kernel_launch(void* const* d_in, const int* in_sizes, int n_in,
                              void* d_out, int out_size)
{
    const float* x     = (const float*)d_in[0];
    const float* W_enc = (const float*)d_in[1];
    const float* b_enc = (const float*)d_in[2];
    const float* Wq    = (const float*)d_in[3];
    const float* bq    = (const float*)d_in[4];
    const float* Wk    = (const float*)d_in[5];
    const float* bk    = (const float*)d_in[6];
    const float* Wv    = (const float*)d_in[7];
    const float* bv    = (const float*)d_in[8];
    const float* Wo    = (const float*)d_in[9];
    const float* bo    = (const float*)d_in[10];
    const float* ocr   = (const float*)d_in[11];
    const float* W1    = (const float*)d_in[12];
    const float* b1    = (const float*)d_in[13];
    const float* W2    = (const float*)d_in[14];
    const float* b2    = (const float*)d_in[15];
    const float* ln_g  = (const float*)d_in[16];
    const float* ln_b  = (const float*)d_in[17];
    float* out = (float*)d_out;

    __half *xh, *mem, *qkv, *ctx, *h1;
    __half *wenc, *wqkv, *wo_nt, *w1, *w2, *wfused;
    float *h2, *bqkv, *b1p;
    cudaGetSymbolAddress((void**)&xh,  g_x);
    cudaGetSymbolAddress((void**)&mem, g_mem);
    cudaGetSymbolAddress((void**)&qkv, g_qkv);
    cudaGetSymbolAddress((void**)&ctx, g_ctx);
    cudaGetSymbolAddress((void**)&h1,  g_h1);
    cudaGetSymbolAddress((void**)&h2,  g_h2);
    cudaGetSymbolAddress((void**)&bqkv, g_bqkv);
    cudaGetSymbolAddress((void**)&b1p, g_b1p);
    cudaGetSymbolAddress((void**)&wenc, g_wenc);
    cudaGetSymbolAddress((void**)&wqkv, g_wqkv);
    cudaGetSymbolAddress((void**)&wo_nt, g_wo_nt);
    cudaGetSymbolAddress((void**)&w1, g_w1);
    cudaGetSymbolAddress((void**)&w2, g_w2);
    cudaGetSymbolAddress((void**)&wfused, g_wfused);

    cudaFuncSetAttribute(fused_attn_w1, cudaFuncAttributeMaxDynamicSharedMemorySize, GEMM_SMEM);
    cudaFuncSetAttribute(fused_mem_wf,  cudaFuncAttributeMaxDynamicSharedMemorySize, GEMM_SMEM);
    cudaFuncSetAttribute(hgemm_w2_ln,   cudaFuncAttributeMaxDynamicSharedMemorySize, GEMM_SMEM);
    cudaFuncSetAttribute(hgemm<1>, cudaFuncAttributeMaxDynamicSharedMemorySize, GEMM_SMEM);
    cudaFuncSetAttribute(hgemm<4>, cudaFuncAttributeMaxDynamicSharedMemorySize, GEMM_SMEM);

    // 1) single merged prep (also zeroes w2-LN counters)
    prep_all<<<12320, 256>>>(x, W_enc, Wq, Wk, Wv, Wo, W1, W2, bq, bk, bv, bo, b1);
    // 2) FUSED one-wave: mem = x@W_enc + b_enc  ||  wfused = (Wo@W1b)^T
    fused_mem_wf<<<288, 256, GEMM_SMEM>>>(xh, wenc, b_enc, mem, w1, wo_nt, wfused);
    // 3) qkv = mem @ [Wq|Wk|Wv] + b -> scattered [3][B,H,S,64]
    hgemm<1><<<dim3(12, 64), 256, GEMM_SMEM>>>(mem, M_, M_, mem, M_, wqkv, M_, bqkv,
                                               qkv, nullptr, 0, M_);
    // 4) FUSED (attn first, LPT): attention -> ctx  ||  h2 = x @ W1[:1024] + b1'
    fused_attn_w1<<<GX_ATTN + GX_GEMM, 256, GEMM_SMEM>>>(xh, w1, b1p, h2, qkv, ocr, ctx);
    // 5) h1 = gelu(h2 + ctx @ Wfused)
    hgemm<4><<<dim3(8, 64), 256, GEMM_SMEM>>>(ctx, M_, M_, ctx, M_, wfused, M_,
                                              nullptr, h1, h2, D_, M_);
    // 6) h2 = h1 @ W2 + b2, with LayerNorm fused into the last CTA per row-block
    hgemm_w2_ln<<<dim3(8, 64), 256, GEMM_SMEM>>>(h1, w2, b2, h2, ln_g, ln_b, out);
}

// round 16
// speedup vs baseline: 1.0959x; 1.0959x over previous
#include <cuda_runtime.h>
#include <cuda_fp16.h>
#include <math.h>
#include <stdint.h>

#define B_  4
#define S_  2048
#define D_  1024
#define M_  512
#define H_  8
#define R_  (B_*S_)   // 8192 token rows

// ---------------- scratch (device globals: no allocation) ----------------
__device__ __half g_x  [R_*D_];
__device__ __half g_mem[R_*M_];
__device__ __half g_qkv[3*R_*M_];      // [3][B][H][S][64]
__device__ __half g_ctx[R_*M_];
__device__ __half g_h1 [R_*D_];
__device__ float  g_h2 [R_*D_];        // fp32 staging (w1 x-part, then w2 out)
__device__ float  g_bqkv[3*M_];
__device__ float  g_b1p [D_];          // b1 + bo @ W1b
__device__ int    g_rowcnt[64];        // h1 row-block completion counters
// weights transposed [N][K], fp16
__device__ __half g_wenc[M_*D_];
__device__ __half g_wqkv[3*M_*M_];
__device__ __half g_wo_nt[M_*M_];      // Wo NON-transposed fp16 [k][j]
__device__ __half g_w1  [D_*(D_+M_)];
__device__ __half g_w2  [D_*D_];
__device__ __half g_wfused[D_*M_];     // (Wo@W1b)^T  [1024][512]

// ---------------- helpers ----------------
__device__ __forceinline__ uint32_t smem_u32(const void* p) {
    uint32_t a;
    asm("{ .reg .u64 t; cvta.to.shared.u64 t, %1; cvt.u32.u64 %0, t; }" : "=r"(a) : "l"(p));
    return a;
}
__device__ __forceinline__ uint32_t pack_h2(float a, float b) {
    __half2 h = __floats2half2_rn(a, b);
    return *reinterpret_cast<uint32_t*>(&h);
}
__device__ __forceinline__ float gelu_exact(float v) {
    return 0.5f * v * (1.0f + erff(v * 0.70710678118654752440f));
}
__device__ __forceinline__ void cp16(uint32_t s, const void* g) {
    asm volatile("cp.async.cg.shared.global [%0], [%1], 16;" :: "r"(s), "l"(g) : "memory");
}
#define CP_COMMIT() asm volatile("cp.async.commit_group;" ::: "memory")
#define CP_WAIT0()  asm volatile("cp.async.wait_group 0;" ::: "memory")
#define CP_WAIT2()  asm volatile("cp.async.wait_group 2;" ::: "memory")

#define LDSM4(r, addr) \
    asm volatile("ldmatrix.sync.aligned.m8n8.x4.shared.b16 {%0,%1,%2,%3}, [%4];" \
        : "=r"((r)[0]), "=r"((r)[1]), "=r"((r)[2]), "=r"((r)[3]) : "r"(addr))
#define LDSM4T(r, addr) \
    asm volatile("ldmatrix.sync.aligned.m8n8.x4.trans.shared.b16 {%0,%1,%2,%3}, [%4];" \
        : "=r"((r)[0]), "=r"((r)[1]), "=r"((r)[2]), "=r"((r)[3]) : "r"(addr))

__device__ __forceinline__ void mma_f16(float* c, const uint32_t* a, uint32_t b0, uint32_t b1) {
    asm volatile("mma.sync.aligned.m16n8k16.row.col.f32.f16.f16.f32 "
        "{%0,%1,%2,%3}, {%4,%5,%6,%7}, {%8,%9}, {%0,%1,%2,%3};"
        : "+f"(c[0]), "+f"(c[1]), "+f"(c[2]), "+f"(c[3])
        : "r"(a[0]), "r"(a[1]), "r"(a[2]), "r"(a[3]), "r"(b0), "r"(b1));
}

// ---------------- single merged prep kernel --------------------------------
__global__ __launch_bounds__(256)
void prep_all(const float* __restrict__ x,
              const float* __restrict__ wenc, const float* __restrict__ wq,
              const float* __restrict__ wk,   const float* __restrict__ wv,
              const float* __restrict__ wo,   const float* __restrict__ w1,
              const float* __restrict__ w2,
              const float* __restrict__ bq, const float* __restrict__ bk,
              const float* __restrict__ bv, const float* __restrict__ bo,
              const float* __restrict__ b1)
{
    const int blk = blockIdx.x, tid = threadIdx.x;
    if (blk < 3840) {
        __shared__ float t[32][33];
        int tw = blk;
        const float* src; __half* dh; int K, N;
        if      (tw < 512)  {             src = wenc; dh = g_wenc; K = 1024; N = 512; }
        else if (tw < 768)  { tw -= 512;  src = wq; dh = g_wqkv;              K = 512; N = 512; }
        else if (tw < 1024) { tw -= 768;  src = wk; dh = g_wqkv + 512*512;    K = 512; N = 512; }
        else if (tw < 1280) { tw -= 1024; src = wv; dh = g_wqkv + 2*512*512;  K = 512; N = 512; }
        else if (tw < 2816) { tw -= 1280; src = w1; dh = g_w1; K = 1536; N = 1024; }
        else                { tw -= 2816; src = w2; dh = g_w2; K = 1024; N = 1024; }

        const int tilesx = N / 32;
        const int kb = (tw / tilesx) * 32, nb = (tw % tilesx) * 32;
        const int xx = tid & 31, yy = tid >> 5;  // 32 x 8
#pragma unroll
        for (int j = 0; j < 32; j += 8)
            t[yy + j][xx] = src[(size_t)(kb + yy + j) * N + nb + xx];
        __syncthreads();
#pragma unroll
        for (int j = 0; j < 32; j += 8)
            dh[(size_t)(nb + yy + j) * K + kb + xx] = __float2half_rn(t[xx][yy + j]);
        if (blk == 0) {
            for (int i = tid; i < 1536; i += 256)
                g_bqkv[i] = (i < 512) ? bq[i] : (i < 1024) ? bk[i - 512] : bv[i - 1024];
        }
        if (blk == 1 && tid < 64) g_rowcnt[tid] = 0;
    } else if (blk < 12032) {
        const size_t i = ((size_t)(blk - 3840) * 256 + tid) * 4;
        float4 v = *reinterpret_cast<const float4*>(x + i);
        *reinterpret_cast<uint2*>(g_x + i) = make_uint2(pack_h2(v.x, v.y), pack_h2(v.z, v.w));
    } else if (blk < 12288) {
        const size_t i = ((size_t)(blk - 12032) * 256 + tid) * 4;
        float4 v = *reinterpret_cast<const float4*>(wo + i);
        *reinterpret_cast<uint2*>(g_wo_nt + i) = make_uint2(pack_h2(v.x, v.y), pack_h2(v.z, v.w));
    } else {
        __shared__ float red[8][33];
        const int nloc = tid & 31, ksl = tid >> 5;
        const int n = (blk - 12288) * 32 + nloc;
        float s = 0.f;
        const int j0 = ksl * 64;
        for (int j = j0; j < j0 + 64; j++)
            s += bo[j] * w1[(size_t)(1024 + j) * 1024 + n];
        red[ksl][nloc] = s;
        __syncthreads();
        if (ksl == 0) {
            float t2 = b1[n];
#pragma unroll
            for (int q = 0; q < 8; q++) t2 += red[q][nloc];
            g_b1p[n] = t2;
        }
    }
}

// ================== epilogue helper ========================================
template<int EPI>
__device__ __forceinline__ void epi_store(
    float* accp, int r0, int col,
    const float* __restrict__ bias,
    void* __restrict__ o1, const float* __restrict__ i2, int ldc)
{
    const int r1 = r0 + 8;
    float b0v = 0.f, b1v = 0.f;
    if (EPI != 4 && bias) { b0v = bias[col]; b1v = bias[col + 1]; }
    float v00 = accp[0] + b0v, v01 = accp[1] + b1v;
    float v10 = accp[2] + b0v, v11 = accp[3] + b1v;
    if (EPI == 3) {
        float* C = (float*)o1;
        *reinterpret_cast<float2*>(C + (size_t)r0 * ldc + col) = make_float2(v00, v01);
        *reinterpret_cast<float2*>(C + (size_t)r1 * ldc + col) = make_float2(v10, v11);
    } else if (EPI == 4) {
        float2 p0 = *reinterpret_cast<const float2*>(i2 + (size_t)r0 * ldc + col);
        float2 p1 = *reinterpret_cast<const float2*>(i2 + (size_t)r1 * ldc + col);
        v00 = gelu_exact(p0.x + v00); v01 = gelu_exact(p0.y + v01);
        v10 = gelu_exact(p1.x + v10); v11 = gelu_exact(p1.y + v11);
        __half* Ch = (__half*)o1;
        *reinterpret_cast<uint32_t*>(Ch + (size_t)r0 * ldc + col) = pack_h2(v00, v01);
        *reinterpret_cast<uint32_t*>(Ch + (size_t)r1 * ldc + col) = pack_h2(v10, v11);
    } else {
        __half* Ch = (__half*)o1;
        if (EPI == 1) {
            const int tns = col >> 9, rem = col & 511;
            const int hh = rem >> 6, dd = rem & 63;
            size_t oa = ((((size_t)(tns*4 + (r0 >> 11)) * 8 + hh) * 2048 + (r0 & 2047)) * 64 + dd);
            size_t ob = ((((size_t)(tns*4 + (r1 >> 11)) * 8 + hh) * 2048 + (r1 & 2047)) * 64 + dd);
            *reinterpret_cast<uint32_t*>(Ch + oa) = pack_h2(v00, v01);
            *reinterpret_cast<uint32_t*>(Ch + ob) = pack_h2(v10, v11);
        } else {
            *reinterpret_cast<uint32_t*>(Ch + (size_t)r0 * ldc + col) = pack_h2(v00, v01);
            *reinterpret_cast<uint32_t*>(Ch + (size_t)r1 * ldc + col) = pack_h2(v10, v11);
        }
    }
}

// ---------------- fp16 GEMM body 128x128, 8 warps --------------------------
#define ABUF  8192
#define STAGE_BYTES (2*ABUF)
#define GEMM_SMEM (4*STAGE_BYTES)   // 65536

template<int EPI>
__device__ __forceinline__ void hgemm_body(
    char* sm_, int bm, int bn,
    const __half* __restrict__ A1, int lda1, int KA,
    const __half* __restrict__ A2, int lda2,
    const __half* __restrict__ Bt, int ldb,
    const float* __restrict__ bias,
    void* __restrict__ o1, const float* __restrict__ i2, int ldc, int K)
{
    const uint32_t sb = smem_u32(sm_);
    const int tid = threadIdx.x, wid = tid >> 5, lane = tid & 31;
    const int m0 = (wid & 3) * 32, n0 = (wid >> 2) * 64;

    float acc[2][8][4];
#pragma unroll
    for (int i = 0; i < 2; i++)
#pragma unroll
        for (int j = 0; j < 8; j++)
#pragma unroll
            for (int t = 0; t < 4; t++) acc[i][j][t] = 0.f;

    const int cpr = tid >> 2, cpk = tid & 3;
    const uint32_t cps0 = (uint32_t)(cpr * 64 + ((cpk ^ ((cpr >> 1) & 3)) << 4));
    const int cpr1 = cpr + 64;
    const uint32_t cps1 = (uint32_t)(cpr1 * 64 + ((cpk ^ ((cpr1 >> 1) & 3)) << 4));
    const int cpe = cpk * 8;

    auto LOADCP = [&](int c, int buf) {
        const int k0 = c * 32;
        const __half* ap; int ld, ko;
        if (k0 < KA) { ap = A1; ld = lda1; ko = k0; }
        else         { ap = A2; ld = lda2; ko = k0 - KA; }
        const uint32_t st = sb + buf * STAGE_BYTES;
        cp16(st + cps0,        ap + (size_t)(bm + cpr)  * ld + ko + cpe);
        cp16(st + cps1,        ap + (size_t)(bm + cpr1) * ld + ko + cpe);
        cp16(st + ABUF + cps0, Bt + (size_t)(bn + cpr)  * ldb + k0 + cpe);
        cp16(st + ABUF + cps1, Bt + (size_t)(bn + cpr1) * ldb + k0 + cpe);
    };

    const int i4 = lane >> 3, l7 = lane & 7;
    const int khalf = i4 >> 1;
    uint32_t aoffs[2], boffs[4];
#pragma unroll
    for (int mi = 0; mi < 2; mi++) {
        int row = m0 + mi * 16 + ((i4 & 1) << 3) + l7;
        aoffs[mi] = row * 64 + ((khalf ^ ((row >> 1) & 3)) << 4);
    }
#pragma unroll
    for (int nj = 0; nj < 4; nj++) {
        int row = n0 + nj * 16 + ((i4 & 1) << 3) + l7;
        boffs[nj] = row * 64 + ((khalf ^ ((row >> 1) & 3)) << 4);
    }

    const int NC = K >> 5;
    LOADCP(0, 0); CP_COMMIT();
    if (NC > 1) { LOADCP(1, 1); } CP_COMMIT();
    if (NC > 2) { LOADCP(2, 2); } CP_COMMIT();

    for (int c = 0; c < NC; c++) {
        CP_WAIT2();
        __syncthreads();
        const uint32_t bA = sb + (c & 3) * STAGE_BYTES;
        const uint32_t bB = bA + ABUF;

        uint32_t a0[2][4], a1[2][4];
        LDSM4(a0[0], bA + aoffs[0]);
        LDSM4(a0[1], bA + aoffs[1]);
        LDSM4(a1[0], bA + (aoffs[0] ^ 32));
        LDSM4(a1[1], bA + (aoffs[1] ^ 32));

        if (c + 3 < NC) { LOADCP(c + 3, (c + 3) & 3); }
        CP_COMMIT();

        uint32_t bfr[2][4];
        LDSM4(bfr[0], bB + boffs[0]);
#pragma unroll
        for (int t = 0; t < 8; t++) {
            const int nj = t & 3, ks = t >> 2;
            if (t < 7) {
                const int t2 = t + 1;
                LDSM4(bfr[t2 & 1], bB + (boffs[t2 & 3] ^ ((t2 >> 2) << 5)));
            }
            const uint32_t (*av)[4] = ks ? a1 : a0;
            const uint32_t* bv = bfr[t & 1];
            mma_f16(acc[0][nj*2],   av[0], bv[0], bv[2]);
            mma_f16(acc[0][nj*2+1], av[0], bv[1], bv[3]);
            mma_f16(acc[1][nj*2],   av[1], bv[0], bv[2]);
            mma_f16(acc[1][nj*2+1], av[1], bv[1], bv[3]);
        }
    }

    const int g = lane >> 2, tig = lane & 3;
#pragma unroll
    for (int mi = 0; mi < 2; mi++)
#pragma unroll
        for (int nf = 0; nf < 8; nf++)
            epi_store<EPI>(acc[mi][nf],
                           bm + m0 + mi * 16 + g,
                           bn + n0 + nf * 8 + tig * 2,
                           bias, o1, i2, ldc);
}

template<int EPI>
__global__ __launch_bounds__(256, 2)
void hgemm(const __half* __restrict__ A1, int lda1, int KA,
           const __half* __restrict__ A2, int lda2,
           const __half* __restrict__ Bt, int ldb,
           const float* __restrict__ bias,
           void* __restrict__ o1, const float* __restrict__ i2, int ldc, int K)
{
    extern __shared__ char sm_[];
    hgemm_body<EPI>(sm_, blockIdx.y * 128, blockIdx.x * 128,
                    A1, lda1, KA, A2, lda2, Bt, ldb, bias, o1, i2, ldc, K);
}

// -------- fused producer/consumer: h1 = gelu(h2 + ctx@Wfused) -> w2 --------
// ids [0,512): h1 (row-major order: id>>3 = rowblock, id&7 = ntile)
// ids [512,1024): w2, spins until rowblock's 8 producers done.
__global__ __launch_bounds__(256, 2)
void fused_h1_w2(const __half* __restrict__ ctx, const __half* __restrict__ wfused,
                 __half* __restrict__ h1, float* __restrict__ h2,
                 const __half* __restrict__ w2w, const float* __restrict__ b2)
{
    extern __shared__ char sm_[];
    if (blockIdx.x < 512) {
        const int id = blockIdx.x;
        const int bm = (id >> 3) * 128, bn = (id & 7) * 128;
        hgemm_body<4>(sm_, bm, bn, ctx, M_, M_, ctx, M_,
                      wfused, M_, nullptr, h1, h2, D_, M_);
        __threadfence();
        __syncthreads();
        if (threadIdx.x == 0) atomicAdd(&g_rowcnt[bm >> 7], 1);
    } else {
        const int id = blockIdx.x - 512;
        const int bm = (id >> 3) * 128, bn = (id & 7) * 128;
        if (threadIdx.x == 0) {
            volatile int* cnt = &g_rowcnt[bm >> 7];
            while (*cnt < 8) __nanosleep(200);
        }
        __syncthreads();
        __threadfence();
        hgemm_body<3>(sm_, bm, bn, h1 + 0, D_, D_, h1, D_,
                      w2w, D_, b2, h2, nullptr, D_, D_);
    }
}

// -------- fused: mem GEMM (256 CTAs) + wfused GEMM (32 CTAs), one wave ----
__global__ __launch_bounds__(256, 2)
void fused_mem_wf(const __half* __restrict__ xh, const __half* __restrict__ wenc,
                  const float* __restrict__ b_enc, __half* __restrict__ mem,
                  const __half* __restrict__ w1, const __half* __restrict__ wo_nt,
                  __half* __restrict__ wfused)
{
    extern __shared__ char sm_[];
    if (blockIdx.x < 256) {
        const int bn = (blockIdx.x & 3) * 128;
        const int bm = (blockIdx.x >> 2) * 128;
        hgemm_body<0>(sm_, bm, bn, xh, D_, D_, xh, D_, wenc, D_, b_enc,
                      mem, nullptr, M_, D_);
    } else {
        const int idx = blockIdx.x - 256;
        const int bn = (idx & 3) * 128;
        const int bm = (idx >> 2) * 128;
        hgemm_body<0>(sm_, bm, bn, w1 + 1024, D_ + M_, M_, w1 + 1024, D_ + M_,
                      wo_nt, M_, nullptr, wfused, nullptr, M_, M_);
    }
}

// ------- fp16 flash attention body: 128-q tile, 8 warps, fixed-shift ------
#define AT_PITCH 144
#define AT_QBUF  9216
#define AT_Q2BUF (128*AT_PITCH)
#define AT_STAGE (2*AT_QBUF)
#define LOG2E 1.44269504088896f

__device__ __forceinline__ void attn_body(
    char* sm_, int abid,
    const __half* __restrict__ qkv, const float* __restrict__ ocr,
    __half* __restrict__ ctx)
{
    const uint32_t sb = smem_u32(sm_);
    const int tid = threadIdx.x, wid = tid >> 5, lane = tid & 31;
    const int bh = abid >> 4;
    const int qt = abid & 15;
    const int b = bh >> 3, h = bh & 7;
    const int qb = qt * 128;
    const float esc2 = (ocr[h] - 8.0f) * LOG2E;

    const size_t base = (size_t)bh * S_ * 64;
    const size_t ksec = (size_t)R_ * M_;
    const size_t vsec = 2 * ksec;

#pragma unroll
    for (int i = 0; i < 4; i++) {
        int idx = tid + i * 256;
        int r = idx >> 3, cc = (idx & 7) * 16;
        cp16(sb + r * AT_PITCH + cc, (const char*)(qkv + base + (size_t)(qb + r) * 64) + cc);
    }

    auto LOADKV = [&](int c, int buf) {
        const int kb = c * 64;
        const uint32_t st = sb + AT_Q2BUF + buf * AT_STAGE;
#pragma unroll
        for (int i = 0; i < 2; i++) {
            int idx = tid + i * 256;
            int r = idx >> 3, cc = (idx & 7) * 16;
            size_t go = base + (size_t)(kb + r) * 64;
            cp16(st + r * AT_PITCH + cc,            (const char*)(qkv + ksec + go) + cc);
            cp16(st + AT_QBUF + r * AT_PITCH + cc,  (const char*)(qkv + vsec + go) + cc);
        }
    };

    LOADKV(0, 0);
    CP_COMMIT();

    const int q0 = wid * 16;
    const int i4 = lane >> 3, l7 = lane & 7;
    const int g = lane >> 2, tig = lane & 3;
    const uint32_t aoff = (uint32_t)((q0 + ((i4 & 1) << 3) + l7) * AT_PITCH + ((i4 >> 1) << 4));
    uint32_t koffs[4];
#pragma unroll
    for (int nj = 0; nj < 4; nj++)
        koffs[nj] = (uint32_t)((nj * 16 + ((i4 & 1) << 3) + l7) * AT_PITCH + ((i4 >> 1) << 4));
    const int vrow = ((lane >> 4) & 1) * 8 + (lane & 7);
    const int vcol = ((lane >> 3) & 1) * 8;
    uint32_t voffs[4];
#pragma unroll
    for (int ks = 0; ks < 4; ks++)
        voffs[ks] = (uint32_t)(AT_QBUF + (16 * ks + vrow) * AT_PITCH + vcol * 2);

    float l0r = 0.f, l1r = 0.f;
    float o[8][4];
#pragma unroll
    for (int j = 0; j < 8; j++)
#pragma unroll
        for (int t = 0; t < 4; t++) o[j][t] = 0.f;

    uint32_t qv[4][4];
    bool qloaded = false;

    for (int c = 0; c < 32; c++) {
        CP_WAIT0();
        __syncthreads();
        if (c + 1 < 32) { LOADKV(c + 1, (c + 1) & 1); CP_COMMIT(); }

        if (!qloaded) {
#pragma unroll
            for (int ks = 0; ks < 4; ks++) LDSM4(qv[ks], sb + aoff + ks * 32);
            qloaded = true;
        }

        const uint32_t st = sb + AT_Q2BUF + (c & 1) * AT_STAGE;

        float s[8][4];
#pragma unroll
        for (int j = 0; j < 8; j++)
#pragma unroll
            for (int t = 0; t < 4; t++) s[j][t] = 0.f;
#pragma unroll
        for (int ks = 0; ks < 4; ks++) {
#pragma unroll
            for (int nj = 0; nj < 4; nj++) {
                uint32_t kv[4];
                LDSM4(kv, st + koffs[nj] + ks * 32);
                mma_f16(s[nj*2],   qv[ks], kv[0], kv[2]);
                mma_f16(s[nj*2+1], qv[ks], kv[1], kv[3]);
            }
        }

#pragma unroll
        for (int j = 0; j < 8; j++) {
            s[j][0] = exp2f(fmaf(s[j][0], 0.125f * LOG2E, esc2));
            s[j][1] = exp2f(fmaf(s[j][1], 0.125f * LOG2E, esc2));
            s[j][2] = exp2f(fmaf(s[j][2], 0.125f * LOG2E, esc2));
            s[j][3] = exp2f(fmaf(s[j][3], 0.125f * LOG2E, esc2));
            l0r += s[j][0] + s[j][1];
            l1r += s[j][2] + s[j][3];
        }

#pragma unroll
        for (int ks = 0; ks < 4; ks++) {
            uint32_t pa[4];
            pa[0] = pack_h2(s[2*ks][0],   s[2*ks][1]);
            pa[1] = pack_h2(s[2*ks][2],   s[2*ks][3]);
            pa[2] = pack_h2(s[2*ks+1][0], s[2*ks+1][1]);
            pa[3] = pack_h2(s[2*ks+1][2], s[2*ks+1][3]);
#pragma unroll
            for (int d0 = 0; d0 < 4; d0++) {
                uint32_t vv[4];
                LDSM4T(vv, st + voffs[ks] + d0 * 32);
                const int dj = d0 * 2;
                mma_f16(o[dj],   pa, vv[0], vv[2]);
                mma_f16(o[dj+1], pa, vv[1], vv[3]);
            }
        }
    }

    l0r += __shfl_xor_sync(0xffffffffu, l0r, 1);
    l0r += __shfl_xor_sync(0xffffffffu, l0r, 2);
    l1r += __shfl_xor_sync(0xffffffffu, l1r, 1);
    l1r += __shfl_xor_sync(0xffffffffu, l1r, 2);

    const float rl0 = 1.0f / l0r, rl1 = 1.0f / l1r;
    const int row0 = b * S_ + qb + q0 + g;
    const int row1 = row0 + 8;
#pragma unroll
    for (int j = 0; j < 8; j++) {
        const int col = h * 64 + j * 8 + tig * 2;
        *reinterpret_cast<uint32_t*>(ctx + (size_t)row0 * M_ + col) = pack_h2(o[j][0]*rl0, o[j][1]*rl0);
        *reinterpret_cast<uint32_t*>(ctx + (size_t)row1 * M_ + col) = pack_h2(o[j][2]*rl1, o[j][3]*rl1);
    }
}

// ------ fused: attention FIRST (LPT), then x@W1-top GEMM CTAs -------------
#define GX_ATTN 512
#define GX_GEMM 512
__global__ __launch_bounds__(256, 2)
void fused_attn_w1(const __half* __restrict__ xh, const __half* __restrict__ w1,
                   const float* __restrict__ b1p, float* __restrict__ h2o,
                   const __half* __restrict__ qkv, const float* __restrict__ ocr,
                   __half* __restrict__ ctx)
{
    extern __shared__ char sm_[];
    if (blockIdx.x < GX_ATTN) {
        attn_body(sm_, blockIdx.x, qkv, ocr, ctx);
    } else {
        const int id = blockIdx.x - GX_ATTN;
        const int bm = (id & 63) * 128;
        const int bn = (id >> 6) * 128;
        hgemm_body<3>(sm_, bm, bn, xh, D_, D_, xh, D_,
                      w1, D_ + M_, b1p, h2o, nullptr, D_, D_);
    }
}

// ---------------- layernorm ------------------------------------------------
__global__ __launch_bounds__(256)
void layernorm_k(const float* __restrict__ x, const float* __restrict__ g,
                 const float* __restrict__ bb, float* __restrict__ out)
{
    __shared__ float red[8];
    const int row = blockIdx.x, tid = threadIdx.x;
    const float4 v = reinterpret_cast<const float4*>(x + (size_t)row*1024)[tid];

    float s = v.x + v.y + v.z + v.w;
#pragma unroll
    for (int off = 16; off; off >>= 1) s += __shfl_xor_sync(0xffffffffu, s, off);
    if ((tid & 31) == 0) red[tid >> 5] = s;
    __syncthreads();
    if (tid < 32) {
        float t = (tid < 8) ? red[tid] : 0.f;
#pragma unroll
        for (int off = 4; off; off >>= 1) t += __shfl_xor_sync(0xffffffffu, t, off);
        if (tid == 0) red[0] = t;
    }
    __syncthreads();
    const float mean = red[0] * (1.0f / 1024.0f);
    const float dx = v.x - mean, dy = v.y - mean, dz = v.z - mean, dw = v.w - mean;
    float ss = dx*dx + dy*dy + dz*dz + dw*dw;
    __syncthreads();
#pragma unroll
    for (int off = 16; off; off >>= 1) ss += __shfl_xor_sync(0xffffffffu, ss, off);
    if ((tid & 31) == 0) red[tid >> 5] = ss;
    __syncthreads();
    if (tid < 32) {
        float t = (tid < 8) ? red[tid] : 0.f;
#pragma unroll
        for (int off = 4; off; off >>= 1) t += __shfl_xor_sync(0xffffffffu, t, off);
        if (tid == 0) red[0] = t;
    }
    __syncthreads();
    const float inv = rsqrtf(red[0] * (1.0f / 1024.0f) + 1e-5f);
    const int c = tid * 4;
    float4 o;
    o.x = dx * inv * g[c    ] + bb[c    ];
    o.y = dy * inv * g[c + 1] + bb[c + 1];
    o.z = dz * inv * g[c + 2] + bb[c + 2];
    o.w = dw * inv * g[c + 3] + bb[c + 3];
    reinterpret_cast<float4*>(out + (size_t)row*1024)[tid] = o;
}

// ---------------- launch ---------------------------------------------------
extern "C" void kernel_launch(void* const* d_in, const int* in_sizes, int n_in,
                              void* d_out, int out_size)
{
    const float* x     = (const float*)d_in[0];
    const float* W_enc = (const float*)d_in[1];
    const float* b_enc = (const float*)d_in[2];
    const float* Wq    = (const float*)d_in[3];
    const float* bq    = (const float*)d_in[4];
    const float* Wk    = (const float*)d_in[5];
    const float* bk    = (const float*)d_in[6];
    const float* Wv    = (const float*)d_in[7];
    const float* bv    = (const float*)d_in[8];
    const float* Wo    = (const float*)d_in[9];
    const float* bo    = (const float*)d_in[10];
    const float* ocr   = (const float*)d_in[11];
    const float* W1    = (const float*)d_in[12];
    const float* b1    = (const float*)d_in[13];
    const float* W2    = (const float*)d_in[14];
    const float* b2    = (const float*)d_in[15];
    const float* ln_g  = (const float*)d_in[16];
    const float* ln_b  = (const float*)d_in[17];
    float* out = (float*)d_out;

    __half *xh, *mem, *qkv, *ctx, *h1;
    __half *wenc, *wqkv, *wo_nt, *w1, *w2, *wfused;
    float *h2, *bqkv, *b1p;
    cudaGetSymbolAddress((void**)&xh,  g_x);
    cudaGetSymbolAddress((void**)&mem, g_mem);
    cudaGetSymbolAddress((void**)&qkv, g_qkv);
    cudaGetSymbolAddress((void**)&ctx, g_ctx);
    cudaGetSymbolAddress((void**)&h1,  g_h1);
    cudaGetSymbolAddress((void**)&h2,  g_h2);
    cudaGetSymbolAddress((void**)&bqkv, g_bqkv);
    cudaGetSymbolAddress((void**)&b1p, g_b1p);
    cudaGetSymbolAddress((void**)&wenc, g_wenc);
    cudaGetSymbolAddress((void**)&wqkv, g_wqkv);
    cudaGetSymbolAddress((void**)&wo_nt, g_wo_nt);
    cudaGetSymbolAddress((void**)&w1, g_w1);
    cudaGetSymbolAddress((void**)&w2, g_w2);
    cudaGetSymbolAddress((void**)&wfused, g_wfused);

    cudaFuncSetAttribute(fused_attn_w1, cudaFuncAttributeMaxDynamicSharedMemorySize, GEMM_SMEM);
    cudaFuncSetAttribute(fused_mem_wf,  cudaFuncAttributeMaxDynamicSharedMemorySize, GEMM_SMEM);
    cudaFuncSetAttribute(fused_h1_w2,   cudaFuncAttributeMaxDynamicSharedMemorySize, GEMM_SMEM);
    cudaFuncSetAttribute(hgemm<1>, cudaFuncAttributeMaxDynamicSharedMemorySize, GEMM_SMEM);

    // 1) single merged prep (also zeroes h1->w2 counters)
    prep_all<<<12320, 256>>>(x, W_enc, Wq, Wk, Wv, Wo, W1, W2, bq, bk, bv, bo, b1);
    // 2) FUSED one-wave: mem = x@W_enc + b_enc  ||  wfused = (Wo@W1b)^T
    fused_mem_wf<<<288, 256, GEMM_SMEM>>>(xh, wenc, b_enc, mem, w1, wo_nt, wfused);
    // 3) qkv = mem @ [Wq|Wk|Wv] + b -> scattered [3][B,H,S,64]
    hgemm<1><<<dim3(12, 64), 256, GEMM_SMEM>>>(mem, M_, M_, mem, M_, wqkv, M_, bqkv,
                                               qkv, nullptr, 0, M_);
    // 4) FUSED (attn first, LPT): attention -> ctx  ||  h2 = x @ W1[:1024] + b1'
    fused_attn_w1<<<GX_ATTN + GX_GEMM, 256, GEMM_SMEM>>>(xh, w1, b1p, h2, qkv, ocr, ctx);
    // 5+6) FUSED pipeline: h1 = gelu(h2 + ctx@Wfused) --counter--> h2 = h1@W2 + b2
    fused_h1_w2<<<1024, 256, GEMM_SMEM>>>(ctx, wfused, h1, h2, w2, b2);
    // 7) layernorm
    layernorm_k<<<R_, 256>>>(h2, ln_g, ln_b, out);
}

// round 17
// speedup vs baseline: 1.1132x; 1.0159x over previous
#include <cuda_runtime.h>
#include <cuda_fp16.h>
#include <math.h>
#include <stdint.h>

#define B_  4
#define S_  2048
#define D_  1024
#define M_  512
#define H_  8
#define R_  (B_*S_)   // 8192 token rows

// ---------------- scratch (device globals: no allocation) ----------------
__device__ __half g_x  [R_*D_];
__device__ __half g_mem[R_*M_];
__device__ __half g_qkv[3*R_*M_];      // [3][B][H][S][64]
__device__ __half g_ctx[R_*M_];
__device__ __half g_h1 [R_*D_];
__device__ float  g_h2 [R_*D_];        // fp32 staging (w1 x-part, then w2 out)
__device__ float  g_bqkv[3*M_];
__device__ float  g_b1p [D_];          // b1 + bo @ W1b
__device__ int    g_rowcnt[64];        // h1 row-block completion counters
__device__ int    g_bcnt[4];           // qkv per-batch completion counters
// weights transposed [N][K], fp16
__device__ __half g_wenc[M_*D_];
__device__ __half g_wqkv[3*M_*M_];
__device__ __half g_wo_nt[M_*M_];      // Wo NON-transposed fp16 [k][j]
__device__ __half g_w1  [D_*(D_+M_)];
__device__ __half g_w2  [D_*D_];
__device__ __half g_wfused[D_*M_];     // (Wo@W1b)^T  [1024][512]

// ---------------- helpers ----------------
__device__ __forceinline__ uint32_t smem_u32(const void* p) {
    uint32_t a;
    asm("{ .reg .u64 t; cvta.to.shared.u64 t, %1; cvt.u32.u64 %0, t; }" : "=r"(a) : "l"(p));
    return a;
}
__device__ __forceinline__ uint32_t pack_h2(float a, float b) {
    __half2 h = __floats2half2_rn(a, b);
    return *reinterpret_cast<uint32_t*>(&h);
}
__device__ __forceinline__ float gelu_exact(float v) {
    return 0.5f * v * (1.0f + erff(v * 0.70710678118654752440f));
}
__device__ __forceinline__ void cp16(uint32_t s, const void* g) {
    asm volatile("cp.async.cg.shared.global [%0], [%1], 16;" :: "r"(s), "l"(g) : "memory");
}
#define CP_COMMIT() asm volatile("cp.async.commit_group;" ::: "memory")
#define CP_WAIT0()  asm volatile("cp.async.wait_group 0;" ::: "memory")
#define CP_WAIT2()  asm volatile("cp.async.wait_group 2;" ::: "memory")

#define LDSM4(r, addr) \
    asm volatile("ldmatrix.sync.aligned.m8n8.x4.shared.b16 {%0,%1,%2,%3}, [%4];" \
        : "=r"((r)[0]), "=r"((r)[1]), "=r"((r)[2]), "=r"((r)[3]) : "r"(addr))
#define LDSM4T(r, addr) \
    asm volatile("ldmatrix.sync.aligned.m8n8.x4.trans.shared.b16 {%0,%1,%2,%3}, [%4];" \
        : "=r"((r)[0]), "=r"((r)[1]), "=r"((r)[2]), "=r"((r)[3]) : "r"(addr))

__device__ __forceinline__ void mma_f16(float* c, const uint32_t* a, uint32_t b0, uint32_t b1) {
    asm volatile("mma.sync.aligned.m16n8k16.row.col.f32.f16.f16.f32 "
        "{%0,%1,%2,%3}, {%4,%5,%6,%7}, {%8,%9}, {%0,%1,%2,%3};"
        : "+f"(c[0]), "+f"(c[1]), "+f"(c[2]), "+f"(c[3])
        : "r"(a[0]), "r"(a[1]), "r"(a[2]), "r"(a[3]), "r"(b0), "r"(b1));
}

// ---------------- single merged prep kernel --------------------------------
__global__ __launch_bounds__(256)
void prep_all(const float* __restrict__ x,
              const float* __restrict__ wenc, const float* __restrict__ wq,
              const float* __restrict__ wk,   const float* __restrict__ wv,
              const float* __restrict__ wo,   const float* __restrict__ w1,
              const float* __restrict__ w2,
              const float* __restrict__ bq, const float* __restrict__ bk,
              const float* __restrict__ bv, const float* __restrict__ bo,
              const float* __restrict__ b1)
{
    const int blk = blockIdx.x, tid = threadIdx.x;
    if (blk < 3840) {
        __shared__ float t[32][33];
        int tw = blk;
        const float* src; __half* dh; int K, N;
        if      (tw < 512)  {             src = wenc; dh = g_wenc; K = 1024; N = 512; }
        else if (tw < 768)  { tw -= 512;  src = wq; dh = g_wqkv;              K = 512; N = 512; }
        else if (tw < 1024) { tw -= 768;  src = wk; dh = g_wqkv + 512*512;    K = 512; N = 512; }
        else if (tw < 1280) { tw -= 1024; src = wv; dh = g_wqkv + 2*512*512;  K = 512; N = 512; }
        else if (tw < 2816) { tw -= 1280; src = w1; dh = g_w1; K = 1536; N = 1024; }
        else                { tw -= 2816; src = w2; dh = g_w2; K = 1024; N = 1024; }

        const int tilesx = N / 32;
        const int kb = (tw / tilesx) * 32, nb = (tw % tilesx) * 32;
        const int xx = tid & 31, yy = tid >> 5;  // 32 x 8
#pragma unroll
        for (int j = 0; j < 32; j += 8)
            t[yy + j][xx] = src[(size_t)(kb + yy + j) * N + nb + xx];
        __syncthreads();
#pragma unroll
        for (int j = 0; j < 32; j += 8)
            dh[(size_t)(nb + yy + j) * K + kb + xx] = __float2half_rn(t[xx][yy + j]);
        if (blk == 0) {
            for (int i = tid; i < 1536; i += 256)
                g_bqkv[i] = (i < 512) ? bq[i] : (i < 1024) ? bk[i - 512] : bv[i - 1024];
        }
        if (blk == 1) {
            if (tid < 64) g_rowcnt[tid] = 0;
            else if (tid < 68) g_bcnt[tid - 64] = 0;
        }
    } else if (blk < 12032) {
        const size_t i = ((size_t)(blk - 3840) * 256 + tid) * 4;
        float4 v = *reinterpret_cast<const float4*>(x + i);
        *reinterpret_cast<uint2*>(g_x + i) = make_uint2(pack_h2(v.x, v.y), pack_h2(v.z, v.w));
    } else if (blk < 12288) {
        const size_t i = ((size_t)(blk - 12032) * 256 + tid) * 4;
        float4 v = *reinterpret_cast<const float4*>(wo + i);
        *reinterpret_cast<uint2*>(g_wo_nt + i) = make_uint2(pack_h2(v.x, v.y), pack_h2(v.z, v.w));
    } else {
        __shared__ float red[8][33];
        const int nloc = tid & 31, ksl = tid >> 5;
        const int n = (blk - 12288) * 32 + nloc;
        float s = 0.f;
        const int j0 = ksl * 64;
        for (int j = j0; j < j0 + 64; j++)
            s += bo[j] * w1[(size_t)(1024 + j) * 1024 + n];
        red[ksl][nloc] = s;
        __syncthreads();
        if (ksl == 0) {
            float t2 = b1[n];
#pragma unroll
            for (int q = 0; q < 8; q++) t2 += red[q][nloc];
            g_b1p[n] = t2;
        }
    }
}

// ================== epilogue helper ========================================
template<int EPI>
__device__ __forceinline__ void epi_store(
    float* accp, int r0, int col,
    const float* __restrict__ bias,
    void* __restrict__ o1, const float* __restrict__ i2, int ldc)
{
    const int r1 = r0 + 8;
    float b0v = 0.f, b1v = 0.f;
    if (EPI != 4 && bias) { b0v = bias[col]; b1v = bias[col + 1]; }
    float v00 = accp[0] + b0v, v01 = accp[1] + b1v;
    float v10 = accp[2] + b0v, v11 = accp[3] + b1v;
    if (EPI == 3) {
        float* C = (float*)o1;
        *reinterpret_cast<float2*>(C + (size_t)r0 * ldc + col) = make_float2(v00, v01);
        *reinterpret_cast<float2*>(C + (size_t)r1 * ldc + col) = make_float2(v10, v11);
    } else if (EPI == 4) {
        float2 p0 = *reinterpret_cast<const float2*>(i2 + (size_t)r0 * ldc + col);
        float2 p1 = *reinterpret_cast<const float2*>(i2 + (size_t)r1 * ldc + col);
        v00 = gelu_exact(p0.x + v00); v01 = gelu_exact(p0.y + v01);
        v10 = gelu_exact(p1.x + v10); v11 = gelu_exact(p1.y + v11);
        __half* Ch = (__half*)o1;
        *reinterpret_cast<uint32_t*>(Ch + (size_t)r0 * ldc + col) = pack_h2(v00, v01);
        *reinterpret_cast<uint32_t*>(Ch + (size_t)r1 * ldc + col) = pack_h2(v10, v11);
    } else {
        __half* Ch = (__half*)o1;
        if (EPI == 1) {
            const int tns = col >> 9, rem = col & 511;
            const int hh = rem >> 6, dd = rem & 63;
            size_t oa = ((((size_t)(tns*4 + (r0 >> 11)) * 8 + hh) * 2048 + (r0 & 2047)) * 64 + dd);
            size_t ob = ((((size_t)(tns*4 + (r1 >> 11)) * 8 + hh) * 2048 + (r1 & 2047)) * 64 + dd);
            *reinterpret_cast<uint32_t*>(Ch + oa) = pack_h2(v00, v01);
            *reinterpret_cast<uint32_t*>(Ch + ob) = pack_h2(v10, v11);
        } else {
            *reinterpret_cast<uint32_t*>(Ch + (size_t)r0 * ldc + col) = pack_h2(v00, v01);
            *reinterpret_cast<uint32_t*>(Ch + (size_t)r1 * ldc + col) = pack_h2(v10, v11);
        }
    }
}

// ---------------- fp16 GEMM body 128x128, 8 warps --------------------------
#define ABUF  8192
#define STAGE_BYTES (2*ABUF)
#define GEMM_SMEM (4*STAGE_BYTES)   // 65536

template<int EPI>
__device__ __forceinline__ void hgemm_body(
    char* sm_, int bm, int bn,
    const __half* __restrict__ A1, int lda1, int KA,
    const __half* __restrict__ A2, int lda2,
    const __half* __restrict__ Bt, int ldb,
    const float* __restrict__ bias,
    void* __restrict__ o1, const float* __restrict__ i2, int ldc, int K)
{
    const uint32_t sb = smem_u32(sm_);
    const int tid = threadIdx.x, wid = tid >> 5, lane = tid & 31;
    const int m0 = (wid & 3) * 32, n0 = (wid >> 2) * 64;

    float acc[2][8][4];
#pragma unroll
    for (int i = 0; i < 2; i++)
#pragma unroll
        for (int j = 0; j < 8; j++)
#pragma unroll
            for (int t = 0; t < 4; t++) acc[i][j][t] = 0.f;

    const int cpr = tid >> 2, cpk = tid & 3;
    const uint32_t cps0 = (uint32_t)(cpr * 64 + ((cpk ^ ((cpr >> 1) & 3)) << 4));
    const int cpr1 = cpr + 64;
    const uint32_t cps1 = (uint32_t)(cpr1 * 64 + ((cpk ^ ((cpr1 >> 1) & 3)) << 4));
    const int cpe = cpk * 8;

    auto LOADCP = [&](int c, int buf) {
        const int k0 = c * 32;
        const __half* ap; int ld, ko;
        if (k0 < KA) { ap = A1; ld = lda1; ko = k0; }
        else         { ap = A2; ld = lda2; ko = k0 - KA; }
        const uint32_t st = sb + buf * STAGE_BYTES;
        cp16(st + cps0,        ap + (size_t)(bm + cpr)  * ld + ko + cpe);
        cp16(st + cps1,        ap + (size_t)(bm + cpr1) * ld + ko + cpe);
        cp16(st + ABUF + cps0, Bt + (size_t)(bn + cpr)  * ldb + k0 + cpe);
        cp16(st + ABUF + cps1, Bt + (size_t)(bn + cpr1) * ldb + k0 + cpe);
    };

    const int i4 = lane >> 3, l7 = lane & 7;
    const int khalf = i4 >> 1;
    uint32_t aoffs[2], boffs[4];
#pragma unroll
    for (int mi = 0; mi < 2; mi++) {
        int row = m0 + mi * 16 + ((i4 & 1) << 3) + l7;
        aoffs[mi] = row * 64 + ((khalf ^ ((row >> 1) & 3)) << 4);
    }
#pragma unroll
    for (int nj = 0; nj < 4; nj++) {
        int row = n0 + nj * 16 + ((i4 & 1) << 3) + l7;
        boffs[nj] = row * 64 + ((khalf ^ ((row >> 1) & 3)) << 4);
    }

    const int NC = K >> 5;
    LOADCP(0, 0); CP_COMMIT();
    if (NC > 1) { LOADCP(1, 1); } CP_COMMIT();
    if (NC > 2) { LOADCP(2, 2); } CP_COMMIT();

    for (int c = 0; c < NC; c++) {
        CP_WAIT2();
        __syncthreads();
        const uint32_t bA = sb + (c & 3) * STAGE_BYTES;
        const uint32_t bB = bA + ABUF;

        uint32_t a0[2][4], a1[2][4];
        LDSM4(a0[0], bA + aoffs[0]);
        LDSM4(a0[1], bA + aoffs[1]);
        LDSM4(a1[0], bA + (aoffs[0] ^ 32));
        LDSM4(a1[1], bA + (aoffs[1] ^ 32));

        if (c + 3 < NC) { LOADCP(c + 3, (c + 3) & 3); }
        CP_COMMIT();

        uint32_t bfr[2][4];
        LDSM4(bfr[0], bB + boffs[0]);
#pragma unroll
        for (int t = 0; t < 8; t++) {
            const int nj = t & 3, ks = t >> 2;
            if (t < 7) {
                const int t2 = t + 1;
                LDSM4(bfr[t2 & 1], bB + (boffs[t2 & 3] ^ ((t2 >> 2) << 5)));
            }
            const uint32_t (*av)[4] = ks ? a1 : a0;
            const uint32_t* bv = bfr[t & 1];
            mma_f16(acc[0][nj*2],   av[0], bv[0], bv[2]);
            mma_f16(acc[0][nj*2+1], av[0], bv[1], bv[3]);
            mma_f16(acc[1][nj*2],   av[1], bv[0], bv[2]);
            mma_f16(acc[1][nj*2+1], av[1], bv[1], bv[3]);
        }
    }

    const int g = lane >> 2, tig = lane & 3;
#pragma unroll
    for (int mi = 0; mi < 2; mi++)
#pragma unroll
        for (int nf = 0; nf < 8; nf++)
            epi_store<EPI>(acc[mi][nf],
                           bm + m0 + mi * 16 + g,
                           bn + n0 + nf * 8 + tig * 2,
                           bias, o1, i2, ldc);
}

// -------- fused producer/consumer: h1 = gelu(h2 + ctx@Wfused) -> w2 --------
__global__ __launch_bounds__(256, 2)
void fused_h1_w2(const __half* __restrict__ ctx, const __half* __restrict__ wfused,
                 __half* __restrict__ h1, float* __restrict__ h2,
                 const __half* __restrict__ w2w, const float* __restrict__ b2)
{
    extern __shared__ char sm_[];
    if (blockIdx.x < 512) {
        const int id = blockIdx.x;
        const int bm = (id >> 3) * 128, bn = (id & 7) * 128;
        hgemm_body<4>(sm_, bm, bn, ctx, M_, M_, ctx, M_,
                      wfused, M_, nullptr, h1, h2, D_, M_);
        __threadfence();
        __syncthreads();
        if (threadIdx.x == 0) atomicAdd(&g_rowcnt[bm >> 7], 1);
    } else {
        const int id = blockIdx.x - 512;
        const int bm = (id >> 3) * 128, bn = (id & 7) * 128;
        if (threadIdx.x == 0) {
            volatile int* cnt = &g_rowcnt[bm >> 7];
            while (*cnt < 8) __nanosleep(200);
        }
        __syncthreads();
        __threadfence();
        hgemm_body<3>(sm_, bm, bn, h1 + 0, D_, D_, h1, D_,
                      w2w, D_, b2, h2, nullptr, D_, D_);
    }
}

// -------- fused: mem GEMM (256 CTAs) + wfused GEMM (32 CTAs), one wave ----
__global__ __launch_bounds__(256, 2)
void fused_mem_wf(const __half* __restrict__ xh, const __half* __restrict__ wenc,
                  const float* __restrict__ b_enc, __half* __restrict__ mem,
                  const __half* __restrict__ w1, const __half* __restrict__ wo_nt,
                  __half* __restrict__ wfused)
{
    extern __shared__ char sm_[];
    if (blockIdx.x < 256) {
        const int bn = (blockIdx.x & 3) * 128;
        const int bm = (blockIdx.x >> 2) * 128;
        hgemm_body<0>(sm_, bm, bn, xh, D_, D_, xh, D_, wenc, D_, b_enc,
                      mem, nullptr, M_, D_);
    } else {
        const int idx = blockIdx.x - 256;
        const int bn = (idx & 3) * 128;
        const int bm = (idx >> 2) * 128;
        hgemm_body<0>(sm_, bm, bn, w1 + 1024, D_ + M_, M_, w1 + 1024, D_ + M_,
                      wo_nt, M_, nullptr, wfused, nullptr, M_, M_);
    }
}

// ------- fp16 flash attention body: 128-q tile, 8 warps, fixed-shift ------
#define AT_PITCH 144
#define AT_QBUF  9216
#define AT_Q2BUF (128*AT_PITCH)
#define AT_STAGE (2*AT_QBUF)
#define LOG2E 1.44269504088896f

__device__ __forceinline__ void attn_body(
    char* sm_, int abid,
    const __half* __restrict__ qkv, const float* __restrict__ ocr,
    __half* __restrict__ ctx)
{
    const uint32_t sb = smem_u32(sm_);
    const int tid = threadIdx.x, wid = tid >> 5, lane = tid & 31;
    const int bh = abid >> 4;
    const int qt = abid & 15;
    const int b = bh >> 3, h = bh & 7;
    const int qb = qt * 128;
    const float esc2 = (ocr[h] - 8.0f) * LOG2E;

    const size_t base = (size_t)bh * S_ * 64;
    const size_t ksec = (size_t)R_ * M_;
    const size_t vsec = 2 * ksec;

#pragma unroll
    for (int i = 0; i < 4; i++) {
        int idx = tid + i * 256;
        int r = idx >> 3, cc = (idx & 7) * 16;
        cp16(sb + r * AT_PITCH + cc, (const char*)(qkv + base + (size_t)(qb + r) * 64) + cc);
    }

    auto LOADKV = [&](int c, int buf) {
        const int kb = c * 64;
        const uint32_t st = sb + AT_Q2BUF + buf * AT_STAGE;
#pragma unroll
        for (int i = 0; i < 2; i++) {
            int idx = tid + i * 256;
            int r = idx >> 3, cc = (idx & 7) * 16;
            size_t go = base + (size_t)(kb + r) * 64;
            cp16(st + r * AT_PITCH + cc,            (const char*)(qkv + ksec + go) + cc);
            cp16(st + AT_QBUF + r * AT_PITCH + cc,  (const char*)(qkv + vsec + go) + cc);
        }
    };

    LOADKV(0, 0);
    CP_COMMIT();

    const int q0 = wid * 16;
    const int i4 = lane >> 3, l7 = lane & 7;
    const int g = lane >> 2, tig = lane & 3;
    const uint32_t aoff = (uint32_t)((q0 + ((i4 & 1) << 3) + l7) * AT_PITCH + ((i4 >> 1) << 4));
    uint32_t koffs[4];
#pragma unroll
    for (int nj = 0; nj < 4; nj++)
        koffs[nj] = (uint32_t)((nj * 16 + ((i4 & 1) << 3) + l7) * AT_PITCH + ((i4 >> 1) << 4));
    const int vrow = ((lane >> 4) & 1) * 8 + (lane & 7);
    const int vcol = ((lane >> 3) & 1) * 8;
    uint32_t voffs[4];
#pragma unroll
    for (int ks = 0; ks < 4; ks++)
        voffs[ks] = (uint32_t)(AT_QBUF + (16 * ks + vrow) * AT_PITCH + vcol * 2);

    float l0r = 0.f, l1r = 0.f;
    float o[8][4];
#pragma unroll
    for (int j = 0; j < 8; j++)
#pragma unroll
        for (int t = 0; t < 4; t++) o[j][t] = 0.f;

    uint32_t qv[4][4];
    bool qloaded = false;

    for (int c = 0; c < 32; c++) {
        CP_WAIT0();
        __syncthreads();
        if (c + 1 < 32) { LOADKV(c + 1, (c + 1) & 1); CP_COMMIT(); }

        if (!qloaded) {
#pragma unroll
            for (int ks = 0; ks < 4; ks++) LDSM4(qv[ks], sb + aoff + ks * 32);
            qloaded = true;
        }

        const uint32_t st = sb + AT_Q2BUF + (c & 1) * AT_STAGE;

        float s[8][4];
#pragma unroll
        for (int j = 0; j < 8; j++)
#pragma unroll
            for (int t = 0; t < 4; t++) s[j][t] = 0.f;
#pragma unroll
        for (int ks = 0; ks < 4; ks++) {
#pragma unroll
            for (int nj = 0; nj < 4; nj++) {
                uint32_t kv[4];
                LDSM4(kv, st + koffs[nj] + ks * 32);
                mma_f16(s[nj*2],   qv[ks], kv[0], kv[2]);
                mma_f16(s[nj*2+1], qv[ks], kv[1], kv[3]);
            }
        }

#pragma unroll
        for (int j = 0; j < 8; j++) {
            s[j][0] = exp2f(fmaf(s[j][0], 0.125f * LOG2E, esc2));
            s[j][1] = exp2f(fmaf(s[j][1], 0.125f * LOG2E, esc2));
            s[j][2] = exp2f(fmaf(s[j][2], 0.125f * LOG2E, esc2));
            s[j][3] = exp2f(fmaf(s[j][3], 0.125f * LOG2E, esc2));
            l0r += s[j][0] + s[j][1];
            l1r += s[j][2] + s[j][3];
        }

#pragma unroll
        for (int ks = 0; ks < 4; ks++) {
            uint32_t pa[4];
            pa[0] = pack_h2(s[2*ks][0],   s[2*ks][1]);
            pa[1] = pack_h2(s[2*ks][2],   s[2*ks][3]);
            pa[2] = pack_h2(s[2*ks+1][0], s[2*ks+1][1]);
            pa[3] = pack_h2(s[2*ks+1][2], s[2*ks+1][3]);
#pragma unroll
            for (int d0 = 0; d0 < 4; d0++) {
                uint32_t vv[4];
                LDSM4T(vv, st + voffs[ks] + d0 * 32);
                const int dj = d0 * 2;
                mma_f16(o[dj],   pa, vv[0], vv[2]);
                mma_f16(o[dj+1], pa, vv[1], vv[3]);
            }
        }
    }

    l0r += __shfl_xor_sync(0xffffffffu, l0r, 1);
    l0r += __shfl_xor_sync(0xffffffffu, l0r, 2);
    l1r += __shfl_xor_sync(0xffffffffu, l1r, 1);
    l1r += __shfl_xor_sync(0xffffffffu, l1r, 2);

    const float rl0 = 1.0f / l0r, rl1 = 1.0f / l1r;
    const int row0 = b * S_ + qb + q0 + g;
    const int row1 = row0 + 8;
#pragma unroll
    for (int j = 0; j < 8; j++) {
        const int col = h * 64 + j * 8 + tig * 2;
        *reinterpret_cast<uint32_t*>(ctx + (size_t)row0 * M_ + col) = pack_h2(o[j][0]*rl0, o[j][1]*rl0);
        *reinterpret_cast<uint32_t*>(ctx + (size_t)row1 * M_ + col) = pack_h2(o[j][2]*rl1, o[j][3]*rl1);
    }
}

// ------ MEGA: qkv producers -> gated attention -> free w1 GEMM ------------
// ids [0,768):    qkv GEMM, batch-major (rb = id/12); bumps g_bcnt[rb>>4]
// ids [768,1280): attention, gated on g_bcnt[batch] == 192
// ids [1280,1792): x @ W1-top (depends only on prep)
__global__ __launch_bounds__(256, 2)
void fused_qkv_attn_w1(const __half* __restrict__ mem, const __half* __restrict__ wqkv,
                       const float* __restrict__ bqkv, __half* __restrict__ qkv,
                       const float* __restrict__ ocr, __half* __restrict__ ctx,
                       const __half* __restrict__ xh, const __half* __restrict__ w1,
                       const float* __restrict__ b1p, float* __restrict__ h2o)
{
    extern __shared__ char sm_[];
    if (blockIdx.x < 768) {
        const int rb = blockIdx.x / 12, nt = blockIdx.x % 12;
        hgemm_body<1>(sm_, rb * 128, nt * 128, mem, M_, M_, mem, M_,
                      wqkv, M_, bqkv, qkv, nullptr, 0, M_);
        __threadfence();
        __syncthreads();
        if (threadIdx.x == 0) atomicAdd(&g_bcnt[rb >> 4], 1);
    } else if (blockIdx.x < 1280) {
        const int abid = blockIdx.x - 768;
        const int bb = abid >> 7;
        if (threadIdx.x == 0) {
            volatile int* cnt = &g_bcnt[bb];
            while (*cnt < 192) __nanosleep(200);
        }
        __syncthreads();
        __threadfence();
        attn_body(sm_, abid, qkv, ocr, ctx);
    } else {
        const int id = blockIdx.x - 1280;
        const int bm = (id & 63) * 128;
        const int bn = (id >> 6) * 128;
        hgemm_body<3>(sm_, bm, bn, xh, D_, D_, xh, D_,
                      w1, D_ + M_, b1p, h2o, nullptr, D_, D_);
    }
}

// ---------------- layernorm ------------------------------------------------
__global__ __launch_bounds__(256)
void layernorm_k(const float* __restrict__ x, const float* __restrict__ g,
                 const float* __restrict__ bb, float* __restrict__ out)
{
    __shared__ float red[8];
    const int row = blockIdx.x, tid = threadIdx.x;
    const float4 v = reinterpret_cast<const float4*>(x + (size_t)row*1024)[tid];

    float s = v.x + v.y + v.z + v.w;
#pragma unroll
    for (int off = 16; off; off >>= 1) s += __shfl_xor_sync(0xffffffffu, s, off);
    if ((tid & 31) == 0) red[tid >> 5] = s;
    __syncthreads();
    if (tid < 32) {
        float t = (tid < 8) ? red[tid] : 0.f;
#pragma unroll
        for (int off = 4; off; off >>= 1) t += __shfl_xor_sync(0xffffffffu, t, off);
        if (tid == 0) red[0] = t;
    }
    __syncthreads();
    const float mean = red[0] * (1.0f / 1024.0f);
    const float dx = v.x - mean, dy = v.y - mean, dz = v.z - mean, dw = v.w - mean;
    float ss = dx*dx + dy*dy + dz*dz + dw*dw;
    __syncthreads();
#pragma unroll
    for (int off = 16; off; off >>= 1) ss += __shfl_xor_sync(0xffffffffu, ss, off);
    if ((tid & 31) == 0) red[tid >> 5] = ss;
    __syncthreads();
    if (tid < 32) {
        float t = (tid < 8) ? red[tid] : 0.f;
#pragma unroll
        for (int off = 4; off; off >>= 1) t += __shfl_xor_sync(0xffffffffu, t, off);
        if (tid == 0) red[0] = t;
    }
    __syncthreads();
    const float inv = rsqrtf(red[0] * (1.0f / 1024.0f) + 1e-5f);
    const int c = tid * 4;
    float4 o;
    o.x = dx * inv * g[c    ] + bb[c    ];
    o.y = dy * inv * g[c + 1] + bb[c + 1];
    o.z = dz * inv * g[c + 2] + bb[c + 2];
    o.w = dw * inv * g[c + 3] + bb[c + 3];
    reinterpret_cast<float4*>(out + (size_t)row*1024)[tid] = o;
}

// ---------------- launch ---------------------------------------------------
extern "C" void kernel_launch(void* const* d_in, const int* in_sizes, int n_in,
                              void* d_out, int out_size)
{
    const float* x     = (const float*)d_in[0];
    const float* W_enc = (const float*)d_in[1];
    const float* b_enc = (const float*)d_in[2];
    const float* Wq    = (const float*)d_in[3];
    const float* bq    = (const float*)d_in[4];
    const float* Wk    = (const float*)d_in[5];
    const float* bk    = (const float*)d_in[6];
    const float* Wv    = (const float*)d_in[7];
    const float* bv    = (const float*)d_in[8];
    const float* Wo    = (const float*)d_in[9];
    const float* bo    = (const float*)d_in[10];
    const float* ocr   = (const float*)d_in[11];
    const float* W1    = (const float*)d_in[12];
    const float* b1    = (const float*)d_in[13];
    const float* W2    = (const float*)d_in[14];
    const float* b2    = (const float*)d_in[15];
    const float* ln_g  = (const float*)d_in[16];
    const float* ln_b  = (const float*)d_in[17];
    float* out = (float*)d_out;

    __half *xh, *mem, *qkv, *ctx, *h1;
    __half *wenc, *wqkv, *wo_nt, *w1, *w2, *wfused;
    float *h2, *bqkv, *b1p;
    cudaGetSymbolAddress((void**)&xh,  g_x);
    cudaGetSymbolAddress((void**)&mem, g_mem);
    cudaGetSymbolAddress((void**)&qkv, g_qkv);
    cudaGetSymbolAddress((void**)&ctx, g_ctx);
    cudaGetSymbolAddress((void**)&h1,  g_h1);
    cudaGetSymbolAddress((void**)&h2,  g_h2);
    cudaGetSymbolAddress((void**)&bqkv, g_bqkv);
    cudaGetSymbolAddress((void**)&b1p, g_b1p);
    cudaGetSymbolAddress((void**)&wenc, g_wenc);
    cudaGetSymbolAddress((void**)&wqkv, g_wqkv);
    cudaGetSymbolAddress((void**)&wo_nt, g_wo_nt);
    cudaGetSymbolAddress((void**)&w1, g_w1);
    cudaGetSymbolAddress((void**)&w2, g_w2);
    cudaGetSymbolAddress((void**)&wfused, g_wfused);

    cudaFuncSetAttribute(fused_qkv_attn_w1, cudaFuncAttributeMaxDynamicSharedMemorySize, GEMM_SMEM);
    cudaFuncSetAttribute(fused_mem_wf,  cudaFuncAttributeMaxDynamicSharedMemorySize, GEMM_SMEM);
    cudaFuncSetAttribute(fused_h1_w2,   cudaFuncAttributeMaxDynamicSharedMemorySize, GEMM_SMEM);

    // 1) single merged prep (zeroes all pipeline counters)
    prep_all<<<12320, 256>>>(x, W_enc, Wq, Wk, Wv, Wo, W1, W2, bq, bk, bv, bo, b1);
    // 2) FUSED one-wave: mem = x@W_enc + b_enc  ||  wfused = (Wo@W1b)^T
    fused_mem_wf<<<288, 256, GEMM_SMEM>>>(xh, wenc, b_enc, mem, w1, wo_nt, wfused);
    // 3) MEGA: qkv producers -> gated attention -> free W1-top GEMM
    fused_qkv_attn_w1<<<1792, 256, GEMM_SMEM>>>(mem, wqkv, bqkv, qkv,
                                                ocr, ctx, xh, w1, b1p, h2);
    // 4+5) FUSED pipeline: h1 = gelu(h2 + ctx@Wfused) --counter--> h2 = h1@W2 + b2
    fused_h1_w2<<<1024, 256, GEMM_SMEM>>>(ctx, wfused, h1, h2, w2, b2);
    // 6) layernorm
    layernorm_k<<<R_, 256>>>(h2, ln_g, ln_b, out);
}